// round 9
// baseline (speedup 1.0000x reference)
#include <cuda_runtime.h>
#include <stdint.h>

#define C 64
#define MAXN 100000
#define MAXE 1600000
#define SCAN_BLK 1024   // elements per scan block (== threads)

#define TM 128      // nodes per GEMM block tile (gemm_self)
#define KC 32       // k-chunk staged per phase
#define XS 129      // x_s row pitch (floats)
#define WS 68       // w_s row pitch (floats): keeps LDS.128 16B-aligned

#define GN 32       // nodes per fused gather+gemm block (512 threads)
#define AS 68       // agg_s row pitch

// Static device scratch (no runtime allocs allowed)
__device__ int   g_cnt[MAXN];              // degree -> intra-block excl cursor -> end
__device__ int   g_off[MAXN];              // intra-block exclusive start offsets
__device__ int   g_bsum[(MAXN + SCAN_BLK - 1) / SCAN_BLK + 1];  // block bases
__device__ int2  g_edge[MAXE];             // CSR payload: {src, f32-bits(weight)}

// ---------------------------------------------------------------------------
// CSR 1: zero degree counters.
// ---------------------------------------------------------------------------
__global__ void __launch_bounds__(256)
zero_cnt_kernel(int N) {
    int i = blockIdx.x * blockDim.x + threadIdx.x;
    if (i < N) g_cnt[i] = 0;
}

// ---------------------------------------------------------------------------
// CSR 2: histogram of destination nodes.
// edge_index is int32 on device (JAX x64 disabled downcasts int64).
// ---------------------------------------------------------------------------
__global__ void __launch_bounds__(256)
hist_kernel(const int* __restrict__ ei, int E) {
    int e = blockIdx.x * blockDim.x + threadIdx.x;
    if (e < E) atomicAdd(&g_cnt[__ldg(ei + e)], 1);
}

// ---------------------------------------------------------------------------
// CSR 3a: per-block exclusive scan (full-chip parallel, one pass).
// ---------------------------------------------------------------------------
__global__ void __launch_bounds__(SCAN_BLK)
scan_blocks_kernel(int N) {
    __shared__ int wsum[32];
    int tid = threadIdx.x;
    int lane = tid & 31, wid = tid >> 5;
    int i = blockIdx.x * SCAN_BLK + tid;

    int c = (i < N) ? g_cnt[i] : 0;
    int incl = c;
#pragma unroll
    for (int o = 1; o < 32; o <<= 1) {
        int t = __shfl_up_sync(0xFFFFFFFFu, incl, o);
        if (lane >= o) incl += t;
    }
    if (lane == 31) wsum[wid] = incl;
    __syncthreads();
    if (wid == 0) {
        int v = wsum[lane];
        int wi = v;
#pragma unroll
        for (int o = 1; o < 32; o <<= 1) {
            int t = __shfl_up_sync(0xFFFFFFFFu, wi, o);
            if (lane >= o) wi += t;
        }
        wsum[lane] = wi - v;
        if (lane == 31) g_bsum[blockIdx.x] = wi;
    }
    __syncthreads();
    int excl = wsum[wid] + (incl - c);
    if (i < N) { g_off[i] = excl; g_cnt[i] = excl; }
}

// ---------------------------------------------------------------------------
// CSR 3b: exclusive scan of block totals (B <= 1024, one block).
// ---------------------------------------------------------------------------
__global__ void __launch_bounds__(1024)
scan_tops_kernel(int B) {
    __shared__ int wsum[32];
    int tid = threadIdx.x;
    int lane = tid & 31, wid = tid >> 5;
    int v = (tid < B) ? g_bsum[tid] : 0;
    int incl = v;
#pragma unroll
    for (int o = 1; o < 32; o <<= 1) {
        int t = __shfl_up_sync(0xFFFFFFFFu, incl, o);
        if (lane >= o) incl += t;
    }
    if (lane == 31) wsum[wid] = incl;
    __syncthreads();
    if (wid == 0) {
        int w = wsum[lane];
        int wi = w;
#pragma unroll
        for (int o = 1; o < 32; o <<= 1) {
            int t = __shfl_up_sync(0xFFFFFFFFu, wi, o);
            if (lane >= o) wi += t;
        }
        wsum[lane] = wi - w;
    }
    __syncthreads();
    int excl = wsum[wid] + (incl - v);
    if (tid < B) g_bsum[tid] = excl;
}

// ---------------------------------------------------------------------------
// CSR 4: fill slots via cursor atomics (8B packed store per edge).
// ---------------------------------------------------------------------------
__global__ void __launch_bounds__(256)
fill_kernel(const int* __restrict__ ei,
            const float* __restrict__ ew,
            int E) {
    int e = blockIdx.x * blockDim.x + threadIdx.x;
    if (e >= E) return;
    int dst = __ldg(ei + e);
    int src = __ldg(ei + (size_t)E + e);
    float w = __ldg(ew + e);
    int base = __ldg(g_bsum + (dst >> 10));
    int pos = base + atomicAdd(&g_cnt[dst], 1);
    g_edge[pos] = make_int2(src, __float_as_int(w));
}

// ---------------------------------------------------------------------------
// FUSED gather + neighbor GEMM. Block = 512 threads = 32 nodes x 16 lanes.
// Phase A: lane owns one float4 chunk; walks node's CSR slots, gathers x[src]
//          rows (coalesced 256B, L2-resident), accumulates in registers,
//          stores the agg row ONLY to smem (agg never hits global).
// Phase B: same block computes out[n][:] += agg_s[n][:] @ Wn^T with Wn staged
//          transposed in smem. FFMA phase overlaps other blocks' LSU phase.
// ---------------------------------------------------------------------------
__global__ void __launch_bounds__(512)
fused_gather_gemm_kernel(const float* __restrict__ x,
                         const float* __restrict__ Wn,
                         float* __restrict__ out,
                         int N) {
    __shared__ float agg_s[GN * AS];
    __shared__ float wn_s[C * WS];   // transposed: wn_s[k][j] = Wn[j][k]

    int tid = threadIdx.x;
    int tx = tid & 15, ty = tid >> 4;     // ty in 0..31 -> node slot
    int m0 = blockIdx.x * GN;
    int node = m0 + ty;

    // Stage Wn transposed: 4096 floats, 2 float4 per thread.
#pragma unroll
    for (int it = 0; it < 2; it++) {
        int i = tid + it * 512;           // float4 index, 0..1023
        int j = i >> 4, q = i & 15;       // row j, float4 q within row
        float4 v = reinterpret_cast<const float4*>(Wn)[j * 16 + q];
        wn_s[(4 * q + 0) * WS + j] = v.x;
        wn_s[(4 * q + 1) * WS + j] = v.y;
        wn_s[(4 * q + 2) * WS + j] = v.z;
        wn_s[(4 * q + 3) * WS + j] = v.w;
    }

    // Phase A: gather this node's weighted neighbor sum (chunk tx).
    float4 acc = make_float4(0.f, 0.f, 0.f, 0.f);
    if (node < N) {
        int base = __ldg(g_bsum + (node >> 10));
        int p = base + __ldg(g_off + node);
        int e = base + g_cnt[node];   // end after fill
        for (; p + 2 <= e; p += 2) {
            int2 e0 = __ldg(g_edge + p);
            int2 e1 = __ldg(g_edge + p + 1);
            float w0 = __int_as_float(e0.y);
            float w1 = __int_as_float(e1.y);
            float4 v0 = __ldg(reinterpret_cast<const float4*>(x + (size_t)e0.x * C) + tx);
            float4 v1 = __ldg(reinterpret_cast<const float4*>(x + (size_t)e1.x * C) + tx);
            acc.x = fmaf(w0, v0.x, acc.x); acc.y = fmaf(w0, v0.y, acc.y);
            acc.z = fmaf(w0, v0.z, acc.z); acc.w = fmaf(w0, v0.w, acc.w);
            acc.x = fmaf(w1, v1.x, acc.x); acc.y = fmaf(w1, v1.y, acc.y);
            acc.z = fmaf(w1, v1.z, acc.z); acc.w = fmaf(w1, v1.w, acc.w);
        }
        if (p < e) {
            int2 e0 = __ldg(g_edge + p);
            float w0 = __int_as_float(e0.y);
            float4 v0 = __ldg(reinterpret_cast<const float4*>(x + (size_t)e0.x * C) + tx);
            acc.x = fmaf(w0, v0.x, acc.x); acc.y = fmaf(w0, v0.y, acc.y);
            acc.z = fmaf(w0, v0.z, acc.z); acc.w = fmaf(w0, v0.w, acc.w);
        }
    }
    *reinterpret_cast<float4*>(&agg_s[ty * AS + 4 * tx]) = acc;
    __syncthreads();

    // Phase B: out[node][4tx..4tx+3] += agg_s[node][:] @ Wn^T[:, 4tx..4tx+3]
    if (node < N) {
        float4 prev = reinterpret_cast<const float4*>(out)[(size_t)node * 16 + tx];
        float o0 = prev.x, o1 = prev.y, o2 = prev.z, o3 = prev.w;
#pragma unroll 16
        for (int k = 0; k < C; k++) {
            float a = agg_s[ty * AS + k];                    // broadcast LDS
            float4 b = *reinterpret_cast<const float4*>(&wn_s[k * WS + 4 * tx]);
            o0 = fmaf(a, b.x, o0);
            o1 = fmaf(a, b.y, o1);
            o2 = fmaf(a, b.z, o2);
            o3 = fmaf(a, b.w, o3);
        }
        reinterpret_cast<float4*>(out)[(size_t)node * 16 + tx] =
            make_float4(o0, o1, o2, o3);
    }
}

// ---------------------------------------------------------------------------
// Tiled GEMM (R6 proven) for the self term only:
//   out[tile] = x[tile] @ Ws^T + (bs + bn)
// ---------------------------------------------------------------------------
__global__ void __launch_bounds__(256)
gemm_self_kernel(const float* __restrict__ x,
                 const float* __restrict__ Ws,
                 const float* __restrict__ bs,
                 const float* __restrict__ bn,
                 float* __restrict__ out,
                 int N) {
    __shared__ float x_s[KC * XS];
    __shared__ float w_s[KC * WS];

    int tid = threadIdx.x;
    int tx = tid & 15, ty = tid >> 4;
    int m0 = blockIdx.x * TM;

    float acc[2][4][4];
#pragma unroll
    for (int h = 0; h < 2; h++)
#pragma unroll
        for (int r = 0; r < 4; r++)
#pragma unroll
            for (int s = 0; s < 4; s++) acc[h][r][s] = 0.f;

#pragma unroll 1
    for (int kc = 0; kc < 2; kc++) {
        __syncthreads();
#pragma unroll
        for (int it = 0; it < 4; it++) {
            int i = tid + it * 256;
            int m = i >> 3, q = i & 7;
            float4 v = make_float4(0.f, 0.f, 0.f, 0.f);
            if (m0 + m < N)
                v = reinterpret_cast<const float4*>(x)[(size_t)(m0 + m) * 16 + kc * 8 + q];
            x_s[(4 * q + 0) * XS + m] = v.x;
            x_s[(4 * q + 1) * XS + m] = v.y;
            x_s[(4 * q + 2) * XS + m] = v.z;
            x_s[(4 * q + 3) * XS + m] = v.w;
        }
#pragma unroll
        for (int it = 0; it < 2; it++) {
            int i = tid + it * 256;
            int j = i >> 3, q = i & 7;
            float4 v = reinterpret_cast<const float4*>(Ws)[j * 16 + kc * 8 + q];
            w_s[(4 * q + 0) * WS + j] = v.x;
            w_s[(4 * q + 1) * WS + j] = v.y;
            w_s[(4 * q + 2) * WS + j] = v.z;
            w_s[(4 * q + 3) * WS + j] = v.w;
        }
        __syncthreads();

#pragma unroll 8
        for (int k = 0; k < KC; k++) {
            float4 b = *reinterpret_cast<const float4*>(&w_s[k * WS + 4 * tx]);
            float a0[4], a1[4];
#pragma unroll
            for (int r = 0; r < 4; r++) {
                a0[r] = x_s[k * XS + 4 * ty + r];
                a1[r] = x_s[k * XS + 64 + 4 * ty + r];
            }
#pragma unroll
            for (int r = 0; r < 4; r++) {
                acc[0][r][0] = fmaf(a0[r], b.x, acc[0][r][0]);
                acc[0][r][1] = fmaf(a0[r], b.y, acc[0][r][1]);
                acc[0][r][2] = fmaf(a0[r], b.z, acc[0][r][2]);
                acc[0][r][3] = fmaf(a0[r], b.w, acc[0][r][3]);
                acc[1][r][0] = fmaf(a1[r], b.x, acc[1][r][0]);
                acc[1][r][1] = fmaf(a1[r], b.y, acc[1][r][1]);
                acc[1][r][2] = fmaf(a1[r], b.z, acc[1][r][2]);
                acc[1][r][3] = fmaf(a1[r], b.w, acc[1][r][3]);
            }
        }
    }

    float4 bias;
    bias.x = __ldg(bs + 4 * tx + 0) + __ldg(bn + 4 * tx + 0);
    bias.y = __ldg(bs + 4 * tx + 1) + __ldg(bn + 4 * tx + 1);
    bias.z = __ldg(bs + 4 * tx + 2) + __ldg(bn + 4 * tx + 2);
    bias.w = __ldg(bs + 4 * tx + 3) + __ldg(bn + 4 * tx + 3);

#pragma unroll
    for (int h = 0; h < 2; h++) {
#pragma unroll
        for (int r = 0; r < 4; r++) {
            int m = m0 + h * 64 + 4 * ty + r;
            if (m < N) {
                float4 o = make_float4(acc[h][r][0] + bias.x, acc[h][r][1] + bias.y,
                                       acc[h][r][2] + bias.z, acc[h][r][3] + bias.w);
                reinterpret_cast<float4*>(out)[(size_t)m * 16 + tx] = o;
            }
        }
    }
}

// ---------------------------------------------------------------------------
// Inputs (metadata order): x[N*64] f32, edge_index[2*E] i32, edge_weight[E] f32,
// W_self[64*64] f32, b_self[64] f32, W_neigh[64*64] f32, b_neigh[64] f32,
// num_nodes (scalar, unused). Output: float32 [N*64].
//
// Side stream: gemm_self (hidden under CSR build). Main: CSR build; join;
// fused gather+neigh-GEMM (agg never leaves smem).
// ---------------------------------------------------------------------------
extern "C" void kernel_launch(void* const* d_in, const int* in_sizes, int n_in,
                              void* d_out, int out_size) {
    const float* x  = (const float*)d_in[0];
    const int*   ei = (const int*)d_in[1];
    const float* ew = (const float*)d_in[2];
    const float* Ws = (const float*)d_in[3];
    const float* bs = (const float*)d_in[4];
    const float* Wn = (const float*)d_in[5];
    const float* bn = (const float*)d_in[6];
    float* out = (float*)d_out;

    int N = in_sizes[0] / C;
    int E = in_sizes[2];
    if (E > MAXE) E = MAXE;  // static scratch bound (problem has E=1.6M)
    int nTiles = (N + TM - 1) / TM;
    int nScan = (N + SCAN_BLK - 1) / SCAN_BLK;
    int nFused = (N + GN - 1) / GN;

    static cudaStream_t s_side = nullptr;
    static cudaEvent_t ev_fork = nullptr, ev_join = nullptr;
    if (s_side == nullptr) {
        cudaStreamCreateWithFlags(&s_side, cudaStreamNonBlocking);
        cudaEventCreateWithFlags(&ev_fork, cudaEventDisableTiming);
        cudaEventCreateWithFlags(&ev_join, cudaEventDisableTiming);
    }

    // Fork: side stream branches off the main (captured) stream.
    cudaEventRecord(ev_fork, 0);
    cudaStreamWaitEvent(s_side, ev_fork, 0);

    // Side stream: out = x@Ws^T + (bs+bn)   [hidden under CSR build]
    gemm_self_kernel<<<nTiles, 256, 0, s_side>>>(x, Ws, bs, bn, out, N);
    cudaEventRecord(ev_join, s_side);

    // Main stream: CSR build
    zero_cnt_kernel<<<(N + 255) / 256, 256>>>(N);
    hist_kernel<<<(E + 255) / 256, 256>>>(ei, E);
    scan_blocks_kernel<<<nScan, SCAN_BLK>>>(N);
    scan_tops_kernel<<<1, 1024>>>(nScan);
    fill_kernel<<<(E + 255) / 256, 256>>>(ei, ew, E);

    // Join (fused kernel reads out written by gemm_self), then fused pass.
    cudaStreamWaitEvent(0, ev_join, 0);
    fused_gather_gemm_kernel<<<nFused, 512>>>(x, Wn, out, N);
}

// round 10
// speedup vs baseline: 1.2087x; 1.2087x over previous
#include <cuda_runtime.h>
#include <stdint.h>

#define C 64
#define MAXN 100000
#define MAXE 1600000
#define SCAN_BLK 1024   // elements per scan block (== threads)

#define TM 128      // nodes per GEMM block tile
#define KC 32       // k-chunk staged per phase
#define XS 129      // x_s row pitch (floats)
#define WS 68       // w_s row pitch (floats): keeps LDS.128 16B-aligned

// Static device scratch (no runtime allocs allowed)
__device__ float g_agg[(size_t)MAXN * C];  // neighbor aggregation
__device__ int   g_cnt[MAXN];              // degree -> intra-block cursor -> end
__device__ int   g_off[MAXN];              // intra-block exclusive start offsets
__device__ int   g_bsum[(MAXN + SCAN_BLK - 1) / SCAN_BLK + 1];  // block bases
__device__ int2  g_edge[MAXE];             // CSR payload: {src, f32-bits(weight)}

// ---------------------------------------------------------------------------
// CSR 1: zero degree counters.
// ---------------------------------------------------------------------------
__global__ void __launch_bounds__(256)
zero_cnt_kernel(int N) {
    int i = blockIdx.x * blockDim.x + threadIdx.x;
    if (i < N) g_cnt[i] = 0;
}

// ---------------------------------------------------------------------------
// CSR 2: histogram of destination nodes.
// edge_index is int32 on device (JAX x64 disabled downcasts int64).
// ---------------------------------------------------------------------------
__global__ void __launch_bounds__(256)
hist_kernel(const int* __restrict__ ei, int E) {
    int e = blockIdx.x * blockDim.x + threadIdx.x;
    if (e < E) atomicAdd(&g_cnt[__ldg(ei + e)], 1);
}

// ---------------------------------------------------------------------------
// CSR 3a: per-block exclusive scan (full-chip parallel, one pass).
// ---------------------------------------------------------------------------
__global__ void __launch_bounds__(SCAN_BLK)
scan_blocks_kernel(int N) {
    __shared__ int wsum[32];
    int tid = threadIdx.x;
    int lane = tid & 31, wid = tid >> 5;
    int i = blockIdx.x * SCAN_BLK + tid;

    int c = (i < N) ? g_cnt[i] : 0;
    int incl = c;
#pragma unroll
    for (int o = 1; o < 32; o <<= 1) {
        int t = __shfl_up_sync(0xFFFFFFFFu, incl, o);
        if (lane >= o) incl += t;
    }
    if (lane == 31) wsum[wid] = incl;
    __syncthreads();
    if (wid == 0) {
        int v = wsum[lane];
        int wi = v;
#pragma unroll
        for (int o = 1; o < 32; o <<= 1) {
            int t = __shfl_up_sync(0xFFFFFFFFu, wi, o);
            if (lane >= o) wi += t;
        }
        wsum[lane] = wi - v;
        if (lane == 31) g_bsum[blockIdx.x] = wi;
    }
    __syncthreads();
    int excl = wsum[wid] + (incl - c);
    if (i < N) { g_off[i] = excl; g_cnt[i] = excl; }
}

// ---------------------------------------------------------------------------
// CSR 3b: exclusive scan of block totals (B <= 1024, one block).
// ---------------------------------------------------------------------------
__global__ void __launch_bounds__(1024)
scan_tops_kernel(int B) {
    __shared__ int wsum[32];
    int tid = threadIdx.x;
    int lane = tid & 31, wid = tid >> 5;
    int v = (tid < B) ? g_bsum[tid] : 0;
    int incl = v;
#pragma unroll
    for (int o = 1; o < 32; o <<= 1) {
        int t = __shfl_up_sync(0xFFFFFFFFu, incl, o);
        if (lane >= o) incl += t;
    }
    if (lane == 31) wsum[wid] = incl;
    __syncthreads();
    if (wid == 0) {
        int w = wsum[lane];
        int wi = w;
#pragma unroll
        for (int o = 1; o < 32; o <<= 1) {
            int t = __shfl_up_sync(0xFFFFFFFFu, wi, o);
            if (lane >= o) wi += t;
        }
        wsum[lane] = wi - w;
    }
    __syncthreads();
    int excl = wsum[wid] + (incl - v);
    if (tid < B) g_bsum[tid] = excl;
}

// ---------------------------------------------------------------------------
// CSR 4: fill slots via cursor atomics (8B packed store per edge).
// ---------------------------------------------------------------------------
__global__ void __launch_bounds__(256)
fill_kernel(const int* __restrict__ ei,
            const float* __restrict__ ew,
            int E) {
    int e = blockIdx.x * blockDim.x + threadIdx.x;
    if (e >= E) return;
    int dst = __ldg(ei + e);
    int src = __ldg(ei + (size_t)E + e);
    float w = __ldg(ew + e);
    int base = __ldg(g_bsum + (dst >> 10));
    int pos = base + atomicAdd(&g_cnt[dst], 1);
    g_edge[pos] = make_int2(src, __float_as_int(w));
}

// ---------------------------------------------------------------------------
// Gather over node range [n0, n1): 16 lanes per node, lane owns one float4
// chunk. Walks CSR slots (8B broadcast loads), gathers x[src] rows (coalesced
// 256B, L2-resident), register accumulation, ONE plain store. No atomics.
// ---------------------------------------------------------------------------
__global__ void __launch_bounds__(256)
gather_kernel(const float* __restrict__ x, int n0, int n1) {
    long long t = (long long)blockIdx.x * blockDim.x + threadIdx.x;
    int node = n0 + (int)(t >> 4);
    if (node >= n1) return;
    int lane = (int)t & 15;

    int base = __ldg(g_bsum + (node >> 10));
    int p = base + __ldg(g_off + node);
    int e = base + g_cnt[node];

    float4 acc = make_float4(0.f, 0.f, 0.f, 0.f);
    for (; p + 2 <= e; p += 2) {
        int2 e0 = __ldg(g_edge + p);
        int2 e1 = __ldg(g_edge + p + 1);
        float w0 = __int_as_float(e0.y);
        float w1 = __int_as_float(e1.y);
        float4 v0 = __ldg(reinterpret_cast<const float4*>(x + (size_t)e0.x * C) + lane);
        float4 v1 = __ldg(reinterpret_cast<const float4*>(x + (size_t)e1.x * C) + lane);
        acc.x = fmaf(w0, v0.x, acc.x); acc.y = fmaf(w0, v0.y, acc.y);
        acc.z = fmaf(w0, v0.z, acc.z); acc.w = fmaf(w0, v0.w, acc.w);
        acc.x = fmaf(w1, v1.x, acc.x); acc.y = fmaf(w1, v1.y, acc.y);
        acc.z = fmaf(w1, v1.z, acc.z); acc.w = fmaf(w1, v1.w, acc.w);
    }
    if (p < e) {
        int2 e0 = __ldg(g_edge + p);
        float w0 = __int_as_float(e0.y);
        float4 v0 = __ldg(reinterpret_cast<const float4*>(x + (size_t)e0.x * C) + lane);
        acc.x = fmaf(w0, v0.x, acc.x); acc.y = fmaf(w0, v0.y, acc.y);
        acc.z = fmaf(w0, v0.z, acc.z); acc.w = fmaf(w0, v0.w, acc.w);
    }
    reinterpret_cast<float4*>(g_agg)[(size_t)node * 16 + lane] = acc;
}

// ---------------------------------------------------------------------------
// Tiled GEMM core (R6/R8 proven): 256 threads, 128x64 tile, 8x4 micro-tile.
// ---------------------------------------------------------------------------
__device__ __forceinline__ void gemm_tile_core(
    const float* __restrict__ src, const float* __restrict__ W,
    float* x_s, float* w_s, float acc[2][4][4],
    int m0, int N, int tid, int tx, int ty)
{
#pragma unroll 1
    for (int kc = 0; kc < 2; kc++) {
        __syncthreads();
#pragma unroll
        for (int it = 0; it < 4; it++) {
            int i = tid + it * 256;
            int m = i >> 3, q = i & 7;
            float4 v = make_float4(0.f, 0.f, 0.f, 0.f);
            if (m0 + m < N)
                v = reinterpret_cast<const float4*>(src)[(size_t)(m0 + m) * 16 + kc * 8 + q];
            x_s[(4 * q + 0) * XS + m] = v.x;
            x_s[(4 * q + 1) * XS + m] = v.y;
            x_s[(4 * q + 2) * XS + m] = v.z;
            x_s[(4 * q + 3) * XS + m] = v.w;
        }
#pragma unroll
        for (int it = 0; it < 2; it++) {
            int i = tid + it * 256;
            int j = i >> 3, q = i & 7;
            float4 v = reinterpret_cast<const float4*>(W)[j * 16 + kc * 8 + q];
            w_s[(4 * q + 0) * WS + j] = v.x;
            w_s[(4 * q + 1) * WS + j] = v.y;
            w_s[(4 * q + 2) * WS + j] = v.z;
            w_s[(4 * q + 3) * WS + j] = v.w;
        }
        __syncthreads();

#pragma unroll 8
        for (int k = 0; k < KC; k++) {
            float4 b = *reinterpret_cast<const float4*>(&w_s[k * WS + 4 * tx]);
            float a0[4], a1[4];
#pragma unroll
            for (int r = 0; r < 4; r++) {
                a0[r] = x_s[k * XS + 4 * ty + r];
                a1[r] = x_s[k * XS + 64 + 4 * ty + r];
            }
#pragma unroll
            for (int r = 0; r < 4; r++) {
                acc[0][r][0] = fmaf(a0[r], b.x, acc[0][r][0]);
                acc[0][r][1] = fmaf(a0[r], b.y, acc[0][r][1]);
                acc[0][r][2] = fmaf(a0[r], b.z, acc[0][r][2]);
                acc[0][r][3] = fmaf(a0[r], b.w, acc[0][r][3]);
                acc[1][r][0] = fmaf(a1[r], b.x, acc[1][r][0]);
                acc[1][r][1] = fmaf(a1[r], b.y, acc[1][r][1]);
                acc[1][r][2] = fmaf(a1[r], b.z, acc[1][r][2]);
                acc[1][r][3] = fmaf(a1[r], b.w, acc[1][r][3]);
            }
        }
    }
}

// ---------------------------------------------------------------------------
// GEMM self: out[tile] = x[tile] @ Ws^T + (bs + bn)   [side stream, hidden]
// ---------------------------------------------------------------------------
__global__ void __launch_bounds__(256)
gemm_self_kernel(const float* __restrict__ x,
                 const float* __restrict__ Ws,
                 const float* __restrict__ bs,
                 const float* __restrict__ bn,
                 float* __restrict__ out,
                 int N) {
    __shared__ float x_s[KC * XS];
    __shared__ float w_s[KC * WS];

    int tid = threadIdx.x;
    int tx = tid & 15, ty = tid >> 4;
    int m0 = blockIdx.x * TM;

    float acc[2][4][4];
#pragma unroll
    for (int h = 0; h < 2; h++)
#pragma unroll
        for (int r = 0; r < 4; r++)
#pragma unroll
            for (int s = 0; s < 4; s++) acc[h][r][s] = 0.f;

    gemm_tile_core(x, Ws, x_s, w_s, acc, m0, N, tid, tx, ty);

    float4 bias;
    bias.x = __ldg(bs + 4 * tx + 0) + __ldg(bn + 4 * tx + 0);
    bias.y = __ldg(bs + 4 * tx + 1) + __ldg(bn + 4 * tx + 1);
    bias.z = __ldg(bs + 4 * tx + 2) + __ldg(bn + 4 * tx + 2);
    bias.w = __ldg(bs + 4 * tx + 3) + __ldg(bn + 4 * tx + 3);

#pragma unroll
    for (int h = 0; h < 2; h++) {
#pragma unroll
        for (int r = 0; r < 4; r++) {
            int m = m0 + h * 64 + 4 * ty + r;
            if (m < N) {
                float4 o = make_float4(acc[h][r][0] + bias.x, acc[h][r][1] + bias.y,
                                       acc[h][r][2] + bias.z, acc[h][r][3] + bias.w);
                reinterpret_cast<float4*>(out)[(size_t)m * 16 + tx] = o;
            }
        }
    }
}

// ---------------------------------------------------------------------------
// GEMM neigh over node range starting at mbase:
//   out[tile] += agg[tile] @ Wn^T
// ---------------------------------------------------------------------------
__global__ void __launch_bounds__(256)
gemm_neigh_kernel(const float* __restrict__ Wn,
                  float* __restrict__ out,
                  int N, int mbase) {
    __shared__ float x_s[KC * XS];
    __shared__ float w_s[KC * WS];

    int tid = threadIdx.x;
    int tx = tid & 15, ty = tid >> 4;
    int m0 = mbase + blockIdx.x * TM;

    float acc[2][4][4];
#pragma unroll
    for (int h = 0; h < 2; h++)
#pragma unroll
        for (int r = 0; r < 4; r++)
#pragma unroll
            for (int s = 0; s < 4; s++) acc[h][r][s] = 0.f;

    gemm_tile_core(g_agg, Wn, x_s, w_s, acc, m0, N, tid, tx, ty);

#pragma unroll
    for (int h = 0; h < 2; h++) {
#pragma unroll
        for (int r = 0; r < 4; r++) {
            int m = m0 + h * 64 + 4 * ty + r;
            if (m < N) {
                float4 prev = reinterpret_cast<const float4*>(out)[(size_t)m * 16 + tx];
                float4 o = make_float4(prev.x + acc[h][r][0], prev.y + acc[h][r][1],
                                       prev.z + acc[h][r][2], prev.w + acc[h][r][3]);
                reinterpret_cast<float4*>(out)[(size_t)m * 16 + tx] = o;
            }
        }
    }
}

// ---------------------------------------------------------------------------
// Inputs (metadata order): x[N*64] f32, edge_index[2*E] i32, edge_weight[E] f32,
// W_self[64*64] f32, b_self[64] f32, W_neigh[64*64] f32, b_neigh[64] f32,
// num_nodes (scalar, unused). Output: float32 [N*64].
//
// Pipeline:
//   side: gemm_self (hidden under CSR build)  -> gemm_neigh(chunk0) after
//         gather(chunk0), overlapping gather(chunk1) on main.
//   main: CSR build -> gather(chunk0) -> gather(chunk1) -> gemm_neigh(chunk1);
//         final wait on side.
// ---------------------------------------------------------------------------
extern "C" void kernel_launch(void* const* d_in, const int* in_sizes, int n_in,
                              void* d_out, int out_size) {
    const float* x  = (const float*)d_in[0];
    const int*   ei = (const int*)d_in[1];
    const float* ew = (const float*)d_in[2];
    const float* Ws = (const float*)d_in[3];
    const float* bs = (const float*)d_in[4];
    const float* Wn = (const float*)d_in[5];
    const float* bn = (const float*)d_in[6];
    float* out = (float*)d_out;

    int N = in_sizes[0] / C;
    int E = in_sizes[2];
    if (E > MAXE) E = MAXE;  // static scratch bound (problem has E=1.6M)
    int nTiles = (N + TM - 1) / TM;
    int nScan = (N + SCAN_BLK - 1) / SCAN_BLK;

    // Split node range at a TM-aligned midpoint.
    int half = ((N / 2 + TM - 1) / TM) * TM;
    if (half > N) half = N;
    int tiles0 = (half + TM - 1) / TM;
    int tiles1 = nTiles - tiles0;

    static cudaStream_t s_side = nullptr;
    static cudaEvent_t ev_fork = nullptr, ev_g0 = nullptr, ev_n0 = nullptr,
                       ev_self = nullptr;
    if (s_side == nullptr) {
        cudaStreamCreateWithFlags(&s_side, cudaStreamNonBlocking);
        cudaEventCreateWithFlags(&ev_fork, cudaEventDisableTiming);
        cudaEventCreateWithFlags(&ev_g0, cudaEventDisableTiming);
        cudaEventCreateWithFlags(&ev_n0, cudaEventDisableTiming);
        cudaEventCreateWithFlags(&ev_self, cudaEventDisableTiming);
    }

    // Fork side stream off the main (captured) stream.
    cudaEventRecord(ev_fork, 0);
    cudaStreamWaitEvent(s_side, ev_fork, 0);

    // Side: out = x@Ws^T + (bs+bn)   [hidden under CSR build]
    gemm_self_kernel<<<nTiles, 256, 0, s_side>>>(x, Ws, bs, bn, out, N);
    cudaEventRecord(ev_self, s_side);

    // Main: CSR build
    zero_cnt_kernel<<<(N + 255) / 256, 256>>>(N);
    hist_kernel<<<(E + 255) / 256, 256>>>(ei, E);
    scan_blocks_kernel<<<nScan, SCAN_BLK>>>(N);
    scan_tops_kernel<<<1, 1024>>>(nScan);
    fill_kernel<<<(E + 255) / 256, 256>>>(ei, ew, E);

    // Main: gather chunk 0
    {
        long long total = (long long)half * 16;
        int blocks = (int)((total + 255) / 256);
        gather_kernel<<<blocks, 256>>>(x, 0, half);
    }
    cudaEventRecord(ev_g0, 0);

    // Side: gemm_neigh(chunk0) — ordered after gemm_self (same stream) and
    // after gather(chunk0) (event). Overlaps gather(chunk1) on main.
    cudaStreamWaitEvent(s_side, ev_g0, 0);
    if (tiles0 > 0)
        gemm_neigh_kernel<<<tiles0, 256, 0, s_side>>>(Wn, out, N, 0);
    cudaEventRecord(ev_n0, s_side);

    // Main: gather chunk 1
    if (half < N) {
        long long total = (long long)(N - half) * 16;
        int blocks = (int)((total + 255) / 256);
        gather_kernel<<<blocks, 256>>>(x, half, N);
    }

    // Main: gemm_neigh(chunk1) — needs out from gemm_self (event).
    cudaStreamWaitEvent(0, ev_self, 0);
    if (tiles1 > 0)
        gemm_neigh_kernel<<<tiles1, 256>>>(Wn, out, N, half);

    // Join side branch back into main.
    cudaStreamWaitEvent(0, ev_n0, 0);
}